// round 9
// baseline (speedup 1.0000x reference)
#include <cuda_runtime.h>

#define HDIM 768
#define DDIM 16
#define MDIM 50
#define MPAD 56           // padded slot count, 7 per lane of an 8-lane segment
#define KP   9            // key/val row pitch in ull (conflict-free)
#define NJ2  8            // DDIM/2 packed pairs
#define HC   12           // 768 / (32 lanes * 2 cols)
#define TTOK 4
#define NBLK 296
#define NWRP 8

typedef unsigned long long ull;

// ---------- packed f32x2 helpers ----------
__device__ __forceinline__ ull ffma2(ull a, ull b, ull c) {
    ull d;
    asm("fma.rn.f32x2 %0, %1, %2, %3;" : "=l"(d) : "l"(a), "l"(b), "l"(c));
    return d;
}
__device__ __forceinline__ ull add2(ull a, ull b) {
    ull d;
    asm("add.rn.f32x2 %0, %1, %2;" : "=l"(d) : "l"(a), "l"(b));
    return d;
}
__device__ __forceinline__ ull pack2(float lo, float hi) {
    ull r;
    asm("mov.b64 %0, {%1, %2};" : "=l"(r) : "f"(lo), "f"(hi));
    return r;
}
__device__ __forceinline__ ull packbb(float v) {
    ull r;
    asm("mov.b64 %0, {%1, %1};" : "=l"(r) : "f"(v));
    return r;
}
__device__ __forceinline__ void unpack2(ull v, float& lo, float& hi) {
    asm("mov.b64 {%0, %1}, %2;" : "=f"(lo), "=f"(hi) : "l"(v));
}
__device__ __forceinline__ ull shfl64(ull v, int off) {
    return __shfl_xor_sync(0xffffffffu, v, off);
}
__device__ __forceinline__ void prefetchL2(const void* p) {
    asm volatile("prefetch.global.L2 [%0];" :: "l"(p));
}

// LN3 scratch between the two kernels (zero-init device global; allocation-free)
__device__ __align__(16) ull g_memn[(size_t)65536 * NJ2];

// =====================================================================
// Kernel A: per-block weight prep + LN1 + down-proj + LN2 + attention
//           + LN3 -> g_memn (packed)
// =====================================================================
__global__ __launch_bounds__(256, 2) void down_kernel(
    const float* __restrict__ x,
    const float* __restrict__ g1, const float* __restrict__ b1,
    const float* __restrict__ Wd, const float* __restrict__ bd,
    const float* __restrict__ mem,
    const float* __restrict__ Wk, const float* __restrict__ bk,
    const float* __restrict__ Wv, const float* __restrict__ bv,
    const float* __restrict__ g2, const float* __restrict__ b2,
    const float* __restrict__ g3, const float* __restrict__ b3,
    int ntok)
{
    extern __shared__ ull sm[];
    ull* sW2d  = sm;                              // 6144
    ull* sKey2 = sW2d + NJ2 * HDIM;               // 504
    ull* sVal2 = sKey2 + MPAD * KP;               // 504
    float* sC1 = (float*)(sVal2 + MPAD * KP);
    float* sC2 = sC1 + DDIM;
    float* sG2 = sC2 + DDIM;
    float* sB2 = sG2 + DDIM;
    float* sG3 = sB2 + DDIM;
    float* sB3 = sG3 + DDIM;

    const int tid = threadIdx.x;
    const int lane = tid & 31;
    const int warp = tid >> 5;

    // ---------------- per-block weight prep ----------------
    for (int id = tid; id < NJ2 * HDIM; id += 256) {
        int j2 = id / HDIM, i = id % HDIM;
        float gi = g1[i];
        sW2d[id] = pack2(gi * Wd[i * DDIM + 2 * j2], gi * Wd[i * DDIM + 2 * j2 + 1]);
    }
    for (int id = tid; id < MDIM * NJ2; id += 256) {
        int m = id / NJ2, j2 = id % NJ2;
        float ak0 = bk[2 * j2], ak1 = bk[2 * j2 + 1];
        float av0 = bv[2 * j2], av1 = bv[2 * j2 + 1];
        #pragma unroll
        for (int k = 0; k < DDIM; k++) {
            float mv = mem[m * DDIM + k];
            ak0 += mv * Wk[k * DDIM + 2 * j2];
            ak1 += mv * Wk[k * DDIM + 2 * j2 + 1];
            av0 += mv * Wv[k * DDIM + 2 * j2];
            av1 += mv * Wv[k * DDIM + 2 * j2 + 1];
        }
        sKey2[m * KP + j2] = pack2(ak0, ak1);
        sVal2[m * KP + j2] = pack2(av0, av1);
    }
    for (int id = tid; id < (MPAD - MDIM) * NJ2; id += 256) {
        int m = MDIM + id / NJ2, j2 = id % NJ2;
        sKey2[m * KP + j2] = 0ull;
        sVal2[m * KP + j2] = 0ull;
    }
    {
        int j0 = warp * 2;
        ull cA = 0ull, cB = 0ull;
        #pragma unroll
        for (int it = 0; it < HDIM / 32; it++) {
            int i = it * 32 + lane;
            float gi = g1[i], bi = b1[i];
            float w0 = Wd[i * DDIM + j0];
            float w1 = Wd[i * DDIM + j0 + 1];
            cA = add2(cA, pack2(gi * w0, bi * w0));
            cB = add2(cB, pack2(gi * w1, bi * w1));
        }
        #pragma unroll
        for (int off = 16; off > 0; off >>= 1) {
            cA = add2(cA, shfl64(cA, off));
            cB = add2(cB, shfl64(cB, off));
        }
        if (lane == 0) {
            float c1a, c2a, c1b, c2b;
            unpack2(cA, c1a, c2a);
            unpack2(cB, c1b, c2b);
            sC1[j0] = c1a;     sC2[j0] = c2a + bd[j0];
            sC1[j0 + 1] = c1b; sC2[j0 + 1] = c2b + bd[j0 + 1];
        }
    }
    if (tid < DDIM) {
        sG2[tid] = g2[tid]; sB2[tid] = b2[tid];
        sG3[tid] = g3[tid]; sB3[tid] = b3[tid];
    }
    __syncthreads();

    const int sg = lane >> 4;
    const int qb = (lane >> 3) & 1;
    const int tt = lane >> 3;
    const int sl7 = lane & 7;
    const int gw = blockIdx.x * NWRP + warp;
    const int gstride = NBLK * NWRP * TTOK;

    for (int tok0 = gw * TTOK; tok0 < ntok; tok0 += gstride) {
        // ---- prefetch next group's x (12KB contiguous) into L2: overlaps
        // the DRAM fetch of group g+1 with all of group g's compute.
        {
            int ntok0 = tok0 + gstride;
            if (ntok0 + TTOK <= ntok) {
                const float* base = x + (size_t)ntok0 * HDIM;
                #pragma unroll
                for (int p = 0; p < 3; p++)
                    prefetchL2(base + (size_t)(lane + p * 32) * 32);
            }
        }

        int row[TTOK];
        #pragma unroll
        for (int t = 0; t < TTOK; t++) {
            int r = tok0 + t;
            row[t] = (r < ntok) ? r : (ntok - 1);
        }
        const float* xr0 = x + (size_t)row[0] * HDIM;
        const float* xr1 = x + (size_t)row[1] * HDIM;
        const float* xr2 = x + (size_t)row[2] * HDIM;
        const float* xr3 = x + (size_t)row[3] * HDIM;

        // ---- pass 1: LN1 stats + packed down-projection
        ull t2[TTOK][NJ2];
        float s0[TTOK], s1[TTOK];
        #pragma unroll
        for (int t = 0; t < TTOK; t++) {
            s0[t] = 0.f; s1[t] = 0.f;
            #pragma unroll
            for (int j2 = 0; j2 < NJ2; j2++) t2[t][j2] = 0ull;
        }

        #pragma unroll
        for (int c = 0; c < HC; c++) {
            const int i0 = c * 64 + lane * 2;
            float2 xv0 = *reinterpret_cast<const float2*>(xr0 + i0);
            float2 xv1 = *reinterpret_cast<const float2*>(xr1 + i0);
            float2 xv2 = *reinterpret_cast<const float2*>(xr2 + i0);
            float2 xv3 = *reinterpret_cast<const float2*>(xr3 + i0);

            s0[0] += xv0.x + xv0.y;  s1[0] += xv0.x * xv0.x + xv0.y * xv0.y;
            s0[1] += xv1.x + xv1.y;  s1[1] += xv1.x * xv1.x + xv1.y * xv1.y;
            s0[2] += xv2.x + xv2.y;  s1[2] += xv2.x * xv2.x + xv2.y * xv2.y;
            s0[3] += xv3.x + xv3.y;  s1[3] += xv3.x * xv3.x + xv3.y * xv3.y;

            ull xp[TTOK][2];
            xp[0][0] = packbb(xv0.x); xp[0][1] = packbb(xv0.y);
            xp[1][0] = packbb(xv1.x); xp[1][1] = packbb(xv1.y);
            xp[2][0] = packbb(xv2.x); xp[2][1] = packbb(xv2.y);
            xp[3][0] = packbb(xv3.x); xp[3][1] = packbb(xv3.y);

            #pragma unroll
            for (int j2 = 0; j2 < NJ2; j2++) {
                ulonglong2 w = *reinterpret_cast<const ulonglong2*>(sW2d + j2 * HDIM + i0);
                #pragma unroll
                for (int t = 0; t < TTOK; t++) {
                    t2[t][j2] = ffma2(xp[t][0], w.x, t2[t][j2]);
                    t2[t][j2] = ffma2(xp[t][1], w.y, t2[t][j2]);
                }
            }
        }

        // ---- fold reduction: token t -> 8-lane group t
        ull E[NJ2 + 1];
        #pragma unroll
        for (int v = 0; v < NJ2 + 1; v++) {
            ull v0 = (v == 0) ? pack2(s0[0], s1[0]) : t2[0][v - 1];
            ull v1 = (v == 0) ? pack2(s0[1], s1[1]) : t2[1][v - 1];
            ull v2 = (v == 0) ? pack2(s0[2], s1[2]) : t2[2][v - 1];
            ull v3 = (v == 0) ? pack2(s0[3], s1[3]) : t2[3][v - 1];
            ull w0 = add2(v0, shfl64(v0, 16));
            ull w1 = add2(v1, shfl64(v1, 16));
            ull w2 = add2(v2, shfl64(v2, 16));
            ull w3 = add2(v3, shfl64(v3, 16));
            ull ea = sg ? w2 : w0;
            ull eb = sg ? w3 : w1;
            ull ya = add2(ea, shfl64(ea, 8));
            ull yb = add2(eb, shfl64(eb, 8));
            ull e = qb ? yb : ya;
            e = add2(e, shfl64(e, 4));
            e = add2(e, shfl64(e, 2));
            e = add2(e, shfl64(e, 1));
            E[v] = e;
        }

        // ---- middle (per 8-lane segment; 4 tokens in parallel)
        float s0v, s1v;
        unpack2(E[0], s0v, s1v);
        float mean = s0v * (1.f / HDIM);
        float var  = s1v * (1.f / HDIM) - mean * mean;
        float rstd = rsqrtf(var + 1e-12f);

        float dv[DDIM];
        float dsum = 0.f;
        #pragma unroll
        for (int j2 = 0; j2 < NJ2; j2++) {
            float tl, th;
            unpack2(E[1 + j2], tl, th);
            float a = rstd * (tl - mean * sC1[2 * j2])     + sC2[2 * j2];
            float b = rstd * (th - mean * sC1[2 * j2 + 1]) + sC2[2 * j2 + 1];
            dv[2 * j2] = a; dv[2 * j2 + 1] = b;
            dsum += a + b;
        }
        float dmean = dsum * (1.f / DDIM);
        float dvar = 0.f;
        #pragma unroll
        for (int j = 0; j < DDIM; j++) { float df = dv[j] - dmean; dvar += df * df; }
        float drs = rsqrtf(dvar * (1.f / DDIM) + 1e-12f);

        ull qp[NJ2];
        #pragma unroll
        for (int j2 = 0; j2 < NJ2; j2++) {
            float qa = (dv[2 * j2]     - dmean) * drs * sG2[2 * j2]     + sB2[2 * j2];
            float qc = (dv[2 * j2 + 1] - dmean) * drs * sG2[2 * j2 + 1] + sB2[2 * j2 + 1];
            qp[j2] = pack2(qa, qc);
        }

        // attention (no max-shift; uniform scales cancel in LN3)
        float ex[7];
        #pragma unroll
        for (int k = 0; k < 7; k++) {
            const ull* kr = sKey2 + (sl7 + 8 * k) * KP;
            ull acc = 0ull;
            #pragma unroll
            for (int j2 = 0; j2 < NJ2; j2++) acc = ffma2(qp[j2], kr[j2], acc);
            float l, h;
            unpack2(acc, l, h);
            ex[k] = __expf(l + h);
        }
        if (sl7 >= 2) ex[6] = 0.f;

        ull mo[NJ2];
        #pragma unroll
        for (int j2 = 0; j2 < NJ2; j2++) mo[j2] = 0ull;
        #pragma unroll
        for (int k = 0; k < 7; k++) {
            const ull* vr = sVal2 + (sl7 + 8 * k) * KP;
            ull pb = packbb(ex[k]);
            #pragma unroll
            for (int j2 = 0; j2 < NJ2; j2++) mo[j2] = ffma2(pb, vr[j2], mo[j2]);
        }
        #pragma unroll
        for (int off = 4; off > 0; off >>= 1) {
            #pragma unroll
            for (int j2 = 0; j2 < NJ2; j2++)
                mo[j2] = add2(mo[j2], shfl64(mo[j2], off));
        }

        // LN3 on unnormalized mo
        float msum = 0.f;
        #pragma unroll
        for (int j2 = 0; j2 < NJ2; j2++) {
            float l, h;
            unpack2(mo[j2], l, h);
            msum += l + h;
        }
        float mmean = msum * (1.f / DDIM);
        float mvar = 0.f;
        #pragma unroll
        for (int j2 = 0; j2 < NJ2; j2++) {
            float l, h;
            unpack2(mo[j2], l, h);
            float fl = l - mmean, fh = h - mmean;
            mvar += fl * fl + fh * fh;
        }
        float mrs = rsqrtf(mvar * (1.f / DDIM) + 1e-12f);

        ull qo[NJ2];
        #pragma unroll
        for (int j2 = 0; j2 < NJ2; j2++) {
            float l, h;
            unpack2(mo[j2], l, h);
            float oa = (l - mmean) * mrs * sG3[2 * j2]     + sB3[2 * j2];
            float ob = (h - mmean) * mrs * sG3[2 * j2 + 1] + sB3[2 * j2 + 1];
            qo[j2] = pack2(oa, ob);
        }

        const int tok = tok0 + tt;
        ull lo, hi;
        if (sl7 == 0)      { lo = qo[0]; hi = qo[1]; }
        else if (sl7 == 1) { lo = qo[2]; hi = qo[3]; }
        else if (sl7 == 2) { lo = qo[4]; hi = qo[5]; }
        else               { lo = qo[6]; hi = qo[7]; }
        if (sl7 < 4 && tok < ntok) {
            *reinterpret_cast<ulonglong2*>(g_memn + (size_t)tok * NJ2 + 2 * sl7) =
                make_ulonglong2(lo, hi);
        }
    }
}

// =====================================================================
// Kernel B: out = memn @ W_up + b_up — register-resident weights.
// 192 threads, 3 blocks/SM (grid 444): warp w owns cols [w*128,..+128).
// =====================================================================
__global__ __launch_bounds__(192, 3) void up_kernel(
    const float* __restrict__ Wup, const float* __restrict__ bup,
    float* __restrict__ out, int ntok, int tb)
{
    __shared__ ull sQ[128 * NJ2];    // 8 KB

    const int tid = threadIdx.x;
    const int warp = tid >> 5;
    const int lane = tid & 31;
    const int i0 = warp * 128 + lane * 4;

    ull wc0[NJ2], wc1[NJ2], wc2[NJ2], wc3[NJ2];
    #pragma unroll
    for (int j2 = 0; j2 < NJ2; j2++) {
        float4 r0 = *reinterpret_cast<const float4*>(Wup + (2 * j2) * HDIM + i0);
        float4 r1 = *reinterpret_cast<const float4*>(Wup + (2 * j2 + 1) * HDIM + i0);
        wc0[j2] = pack2(r0.x, r1.x);
        wc1[j2] = pack2(r0.y, r1.y);
        wc2[j2] = pack2(r0.z, r1.z);
        wc3[j2] = pack2(r0.w, r1.w);
    }
    const float4 bias = *reinterpret_cast<const float4*>(bup + i0);

    const int tb0 = blockIdx.x * tb;
    int tmax = ntok - tb0;
    if (tmax > tb) tmax = tb;
    if (tmax <= 0) return;

    for (int i = tid; i < tmax * NJ2; i += 192)
        sQ[i] = g_memn[(size_t)tb0 * NJ2 + i];
    __syncthreads();

    #pragma unroll 2
    for (int t = 0; t < tmax; t++) {
        const ull* q = sQ + t * NJ2;
        ulonglong2 q01 = *reinterpret_cast<const ulonglong2*>(q);
        ulonglong2 q23 = *reinterpret_cast<const ulonglong2*>(q + 2);
        ulonglong2 q45 = *reinterpret_cast<const ulonglong2*>(q + 4);
        ulonglong2 q67 = *reinterpret_cast<const ulonglong2*>(q + 6);
        ull a0 = 0ull, a1 = 0ull, a2 = 0ull, a3 = 0ull;

        a0 = ffma2(q01.x, wc0[0], a0); a1 = ffma2(q01.x, wc1[0], a1);
        a2 = ffma2(q01.x, wc2[0], a2); a3 = ffma2(q01.x, wc3[0], a3);
        a0 = ffma2(q01.y, wc0[1], a0); a1 = ffma2(q01.y, wc1[1], a1);
        a2 = ffma2(q01.y, wc2[1], a2); a3 = ffma2(q01.y, wc3[1], a3);
        a0 = ffma2(q23.x, wc0[2], a0); a1 = ffma2(q23.x, wc1[2], a1);
        a2 = ffma2(q23.x, wc2[2], a2); a3 = ffma2(q23.x, wc3[2], a3);
        a0 = ffma2(q23.y, wc0[3], a0); a1 = ffma2(q23.y, wc1[3], a1);
        a2 = ffma2(q23.y, wc2[3], a2); a3 = ffma2(q23.y, wc3[3], a3);
        a0 = ffma2(q45.x, wc0[4], a0); a1 = ffma2(q45.x, wc1[4], a1);
        a2 = ffma2(q45.x, wc2[4], a2); a3 = ffma2(q45.x, wc3[4], a3);
        a0 = ffma2(q45.y, wc0[5], a0); a1 = ffma2(q45.y, wc1[5], a1);
        a2 = ffma2(q45.y, wc2[5], a2); a3 = ffma2(q45.y, wc3[5], a3);
        a0 = ffma2(q67.x, wc0[6], a0); a1 = ffma2(q67.x, wc1[6], a1);
        a2 = ffma2(q67.x, wc2[6], a2); a3 = ffma2(q67.x, wc3[6], a3);
        a0 = ffma2(q67.y, wc0[7], a0); a1 = ffma2(q67.y, wc1[7], a1);
        a2 = ffma2(q67.y, wc2[7], a2); a3 = ffma2(q67.y, wc3[7], a3);

        float l, h;
        float4 o;
        unpack2(a0, l, h); o.x = l + h + bias.x;
        unpack2(a1, l, h); o.y = l + h + bias.y;
        unpack2(a2, l, h); o.z = l + h + bias.z;
        unpack2(a3, l, h); o.w = l + h + bias.w;
        *reinterpret_cast<float4*>(out + (size_t)(tb0 + t) * HDIM + i0) = o;
    }
}

extern "C" void kernel_launch(void* const* d_in, const int* in_sizes, int n_in,
                              void* d_out, int out_size)
{
    const float* x   = (const float*)d_in[0];
    const float* g1  = (const float*)d_in[1];
    const float* b1  = (const float*)d_in[2];
    const float* Wd  = (const float*)d_in[3];
    const float* bd  = (const float*)d_in[4];
    const float* g2  = (const float*)d_in[5];
    const float* b2  = (const float*)d_in[6];
    const float* mem = (const float*)d_in[7];
    const float* Wk  = (const float*)d_in[8];
    const float* bk  = (const float*)d_in[9];
    const float* Wv  = (const float*)d_in[10];
    const float* bv  = (const float*)d_in[11];
    const float* g3  = (const float*)d_in[12];
    const float* b3  = (const float*)d_in[13];
    const float* Wup = (const float*)d_in[14];
    const float* bup = (const float*)d_in[15];
    float* out = (float*)d_out;

    int ntok = in_sizes[0] / HDIM;
    if (ntok > 65536) ntok = 65536;

    size_t smA = (size_t)(NJ2 * HDIM + 2 * MPAD * KP) * sizeof(ull)
               + (size_t)(6 * DDIM) * sizeof(float);
    cudaFuncSetAttribute(down_kernel, cudaFuncAttributeMaxDynamicSharedMemorySize, (int)smA);
    down_kernel<<<NBLK, 256, smA>>>(x, g1, b1, Wd, bd, mem, Wk, bk, Wv, bv,
                                    g2, b2, g3, b3, ntok);

    // 3 blocks/SM for up_kernel: 444 blocks, balanced tiles
    int gridTarget = 444;
    int tb = (ntok + gridTarget - 1) / gridTarget;
    if (tb > 128) tb = 128;
    if (tb < 1) tb = 1;
    int gridB = (ntok + tb - 1) / tb;
    up_kernel<<<gridB, 192>>>(Wup, bup, out, ntok, tb);
}